// round 3
// baseline (speedup 1.0000x reference)
#include <cuda_runtime.h>
#include <cuda_bf16.h>
#include <cuda_fp8.h>
#include <cstdint>

// Problem shape (fixed by dataset)
#define BB 8
#define SS 2048
#define DD 1024
#define OO 1024
#define LCH 256           // scan chunk length
#define NCH (SS / LCH)    // 8 chunks

// Scaling: H = 8*h, C = 1024*c. out = acc / 8192.
#define H_SCALE 8.0f
#define C_SCALE 1024.0f
#define OUT_SCALE (1.0f / 8192.0f)

// ---------------- device scratch (no allocations allowed) ----------------
__device__ float          g_carry[BB * NCH * DD];                 // 256 KB
__device__ __nv_bfloat16  g_hs_hi[(size_t)BB * SS * DD];          // 32 MB  bf16(H)
__device__ unsigned char  g_hs_lo8[(size_t)BB * SS * DD];         // 16 MB  e4m3(H - bf16(H))
__device__ unsigned char  g_hs_q8[(size_t)BB * SS * DD];          // 16 MB  e4m3(H/32)
__device__ __nv_bfloat16  g_bct_hi[(size_t)OO * DD];              // 2 MB   bf16(C)   (BC^T)
__device__ unsigned char  g_bct_hi8[(size_t)OO * DD];             // 1 MB   e4m3(C)
__device__ unsigned char  g_bct_lo8[(size_t)OO * DD];             // 1 MB   e4m3(32*(C - bf16(C)))

// ---------------- helpers --------------------------------------------------
__device__ __forceinline__ uint32_t smem_u32(const void* p) {
    uint32_t a;
    asm("{ .reg .u64 t; cvta.to.shared.u64 t, %1; cvt.u32.u64 %0, t; }"
        : "=r"(a) : "l"(p));
    return a;
}

#define SW128(off) ((off) ^ (((off) >> 3) & 0x70))

#define CP_ASYNC_16(dst_smem, src_gmem) \
    asm volatile("cp.async.cg.shared.global [%0], [%1], 16;" \
                 :: "r"(dst_smem), "l"(src_gmem) : "memory")
#define CP_COMMIT() asm volatile("cp.async.commit_group;" ::: "memory")
#define CP_WAIT_GROUP(n) asm volatile("cp.async.wait_group %0;" :: "n"(n) : "memory")

#define LDSM_X4(r0, r1, r2, r3, addr) \
    asm volatile("ldmatrix.sync.aligned.m8n8.x4.shared.b16 {%0,%1,%2,%3}, [%4];" \
                 : "=r"(r0), "=r"(r1), "=r"(r2), "=r"(r3) : "r"(addr))

#define MMA_BF16(c, a, b) \
    asm volatile("mma.sync.aligned.m16n8k16.row.col.f32.bf16.bf16.f32 " \
                 "{%0,%1,%2,%3}, {%4,%5,%6,%7}, {%8,%9}, {%0,%1,%2,%3};" \
                 : "+f"((c)[0]), "+f"((c)[1]), "+f"((c)[2]), "+f"((c)[3]) \
                 : "r"((a)[0]), "r"((a)[1]), "r"((a)[2]), "r"((a)[3]), \
                   "r"((b)[0]), "r"((b)[1]))

#define MMA_FP8(c, a, b) \
    asm volatile("mma.sync.aligned.m16n8k32.row.col.f32.e4m3.e4m3.f32 " \
                 "{%0,%1,%2,%3}, {%4,%5,%6,%7}, {%8,%9}, {%0,%1,%2,%3};" \
                 : "+f"((c)[0]), "+f"((c)[1]), "+f"((c)[2]), "+f"((c)[3]) \
                 : "r"((a)[0]), "r"((a)[1]), "r"((a)[2]), "r"((a)[3]), \
                   "r"((b)[0]), "r"((b)[1]))

// ---------------- Kernel 1: per-chunk carries (float2/thread) -------------
__global__ void scan_carry_kernel(const float* __restrict__ x,
                                  const float* __restrict__ A) {
    int idx = blockIdx.x * blockDim.x + threadIdx.x;   // B*NCH*DD/2 threads
    int d = (idx & (DD / 2 - 1)) * 2;
    int chunk = (idx >> 9) & (NCH - 1);
    int b = idx >> 12;
    float2 a = *(const float2*)(A + d);
    const float* xp = x + ((size_t)(b * SS + chunk * LCH)) * DD + d;
    float2 h = make_float2(0.0f, 0.0f);
#pragma unroll 8
    for (int i = 0; i < LCH; i++) {
        float2 xv = *(const float2*)(xp + (size_t)i * DD);
        h.x = fmaf(h.x, a.x, xv.x);
        h.y = fmaf(h.y, a.y, xv.y);
    }
    *(float2*)(g_carry + (size_t)((b * NCH + chunk) * DD) + d) = h;
}

// ---------------- Kernel 2: carry-corrected emit --------------------------
__global__ void scan_emit_kernel(const float* __restrict__ x,
                                 const float* __restrict__ A) {
    int idx = blockIdx.x * blockDim.x + threadIdx.x;
    int d = (idx & (DD / 2 - 1)) * 2;
    int chunk = (idx >> 9) & (NCH - 1);
    int b = idx >> 12;
    float2 a = *(const float2*)(A + d);
    float2 aL = a;
#pragma unroll
    for (int s = 0; s < 8; s++) { aL.x *= aL.x; aL.y *= aL.y; }   // a^256
    float2 h = make_float2(0.0f, 0.0f);
    for (int j = 0; j < chunk; j++) {
        float2 cv = *(const float2*)(g_carry + (size_t)((b * NCH + j) * DD) + d);
        h.x = fmaf(h.x, aL.x, cv.x);
        h.y = fmaf(h.y, aL.y, cv.y);
    }
    size_t base = ((size_t)(b * SS + chunk * LCH)) * DD + d;
#pragma unroll 4
    for (int i = 0; i < LCH; i++) {
        size_t off = base + (size_t)i * DD;
        float2 xv = *(const float2*)(x + off);
        h.x = fmaf(h.x, a.x, xv.x);
        h.y = fmaf(h.y, a.y, xv.y);
        float Hx = h.x * H_SCALE, Hy = h.y * H_SCALE;
        __nv_bfloat16 hix = __float2bfloat16_rn(Hx);
        __nv_bfloat16 hiy = __float2bfloat16_rn(Hy);
        __nv_bfloat162 hi2; hi2.x = hix; hi2.y = hiy;
        *(__nv_bfloat162*)(g_hs_hi + off) = hi2;
        float2 lo = make_float2(Hx - __bfloat162float(hix),
                                Hy - __bfloat162float(hiy));
        __nv_fp8x2_storage_t lo8 =
            __nv_cvt_float2_to_fp8x2(lo, __NV_SATFINITE, __NV_E4M3);
        *(__nv_fp8x2_storage_t*)(g_hs_lo8 + off) = lo8;
        float2 q = make_float2(Hx * 0.03125f, Hy * 0.03125f);
        __nv_fp8x2_storage_t q8 =
            __nv_cvt_float2_to_fp8x2(q, __NV_SATFINITE, __NV_E4M3);
        *(__nv_fp8x2_storage_t*)(g_hs_q8 + off) = q8;
    }
}

// ---------------- Kernel 3: BC [D,O] -> BC^T splits [O,D] -----------------
__global__ void bc_transpose_split_kernel(const float* __restrict__ bc) {
    __shared__ float tile[32][33];
    int o0 = blockIdx.x * 32;
    int d0 = blockIdx.y * 32;
    int tx = threadIdx.x, ty = threadIdx.y;    // 32 x 8
#pragma unroll
    for (int j = 0; j < 32; j += 8) {
        tile[ty + j][tx] = bc[(size_t)(d0 + ty + j) * OO + o0 + tx];
    }
    __syncthreads();
#pragma unroll
    for (int j = 0; j < 32; j += 8) {
        float C = tile[tx][ty + j] * C_SCALE;  // = 1024*BC[d0+tx][o0+ty+j]
        size_t oi = (size_t)(o0 + ty + j) * DD + d0 + tx;
        __nv_bfloat16 Chi = __float2bfloat16_rn(C);
        g_bct_hi[oi] = Chi;
        g_bct_hi8[oi] = __nv_cvt_float_to_fp8(C, __NV_SATFINITE, __NV_E4M3);
        float Clo = (C - __bfloat162float(Chi)) * 32.0f;
        g_bct_lo8[oi] = __nv_cvt_float_to_fp8(Clo, __NV_SATFINITE, __NV_E4M3);
    }
}

// ---------------- Kernel 4: pipelined HMMA bf16 + fp8 GEMM ----------------
// acc[r, n] = sum_k H[r, k] * C[k, n] ; out = acc / 8192
#define TM 128
#define TN 128
#define KT 64
#define NKC (DD / KT)        // 16 K-chunks
#define STAGES 3
#define TILE_BYTES (128 * 128)          // each tile: 128 rows x 128B
// stage tiles: 0 = A_hi bf16 (KT cols), 1 = A fp8 [lo8 64B | q8 64B],
//              2 = B_hi bf16,           3 = B fp8 [hi8 64B | lo8 64B]
#define STAGE_BYTES (4 * TILE_BYTES)    // 64 KB
#define SM_GEMM (STAGES * STAGE_BYTES)  // 192 KB

__device__ __forceinline__ void load_stage(uint32_t stage_base, int m0, int n0,
                                           int kc, int tid) {
    int k0 = kc * KT;
#pragma unroll
    for (int i = 0; i < 16; i++) {
        int c = i * 256 + tid;          // 0..4095 ; tile uniform per i
        int tile = c >> 10;             // 0..3
        int rem = c & 1023;
        int row = rem >> 3;
        int ch = rem & 7;
        uint32_t soff = SW128((uint32_t)(row * 128 + ch * 16));
        uint32_t daddr = stage_base + tile * TILE_BYTES + soff;
        const void* gp;
        if (tile == 0) {
            gp = g_hs_hi + (size_t)(m0 + row) * DD + k0 + ch * 8;
        } else if (tile == 1) {
            gp = (ch < 4) ? (const void*)(g_hs_lo8 + (size_t)(m0 + row) * DD + k0 + ch * 16)
                          : (const void*)(g_hs_q8  + (size_t)(m0 + row) * DD + k0 + (ch - 4) * 16);
        } else if (tile == 2) {
            gp = g_bct_hi + (size_t)(n0 + row) * DD + k0 + ch * 8;
        } else {
            gp = (ch < 4) ? (const void*)(g_bct_hi8 + (size_t)(n0 + row) * DD + k0 + ch * 16)
                          : (const void*)(g_bct_lo8 + (size_t)(n0 + row) * DD + k0 + (ch - 4) * 16);
        }
        CP_ASYNC_16(daddr, gp);
    }
}

__global__ __launch_bounds__(256, 1)
void gemm_bf16_fp8_kernel(float* __restrict__ out) {
    extern __shared__ __align__(1024) char smem[];
    uint32_t sb = smem_u32(smem);
    int tid = threadIdx.x;
    int wid = tid >> 5;
    int lane = tid & 31;
    int wm = wid & 3;           // 4 warps along M
    int wn = wid >> 2;          // 2 warps along N
    int m0 = blockIdx.x * TM;
    int n0 = blockIdx.y * TN;

    float acc[2][8][4];
#pragma unroll
    for (int mi = 0; mi < 2; mi++)
#pragma unroll
        for (int ni = 0; ni < 8; ni++)
#pragma unroll
            for (int c = 0; c < 4; c++) acc[mi][ni][c] = 0.0f;

#pragma unroll
    for (int s = 0; s < STAGES - 1; s++) {
        load_stage(sb + s * STAGE_BYTES, m0, n0, s, tid);
        CP_COMMIT();
    }

    int a_row = wm * 32 + (lane & 15);
    int a_chb = ((lane >> 4) & 1) * 16;
    int b_row = wn * 64 + ((lane >> 4) & 1) * 8 + (lane & 7);
    int b_chb = ((lane >> 3) & 1) * 16;

    for (int kc = 0; kc < NKC; kc++) {
        CP_WAIT_GROUP(1);
        __syncthreads();
        if (kc + STAGES - 1 < NKC) {
            load_stage(sb + ((kc + STAGES - 1) % STAGES) * STAGE_BYTES,
                       m0, n0, kc + STAGES - 1, tid);
            CP_COMMIT();
        }

        uint32_t st = sb + (kc % STAGES) * STAGE_BYTES;
        uint32_t s_ahi = st;
        uint32_t s_a8  = st + TILE_BYTES;
        uint32_t s_bhi = st + 2 * TILE_BYTES;
        uint32_t s_b8  = st + 3 * TILE_BYTES;

        // ---- main pass: bf16 H_hi x C_hi (4 k16 steps) ----
#pragma unroll
        for (int ks = 0; ks < KT / 16; ks++) {
            uint32_t a_hi[2][4];
            uint32_t b_hi[8][2];
#pragma unroll
            for (int mi = 0; mi < 2; mi++) {
                uint32_t off = SW128((uint32_t)((a_row + mi * 16) * 128 + ks * 32 + a_chb));
                LDSM_X4(a_hi[mi][0], a_hi[mi][1], a_hi[mi][2], a_hi[mi][3], s_ahi + off);
            }
#pragma unroll
            for (int p = 0; p < 4; p++) {
                uint32_t off = SW128((uint32_t)((b_row + p * 16) * 128 + ks * 32 + b_chb));
                uint32_t t0, t1, t2, t3;
                LDSM_X4(t0, t1, t2, t3, s_bhi + off);
                b_hi[2 * p][0] = t0; b_hi[2 * p][1] = t1;
                b_hi[2 * p + 1][0] = t2; b_hi[2 * p + 1][1] = t3;
            }
#pragma unroll
            for (int mi = 0; mi < 2; mi++)
#pragma unroll
                for (int ni = 0; ni < 8; ni++)
                    MMA_BF16(acc[mi][ni], a_hi[mi], b_hi[ni]);
        }

        // ---- correction passes: fp8 (2 k32 steps) ----
#pragma unroll
        for (int ks = 0; ks < KT / 32; ks++) {
            uint32_t a_lo8[2][4], a_q8[2][4];
            uint32_t b_h8[8][2], b_l8[8][2];
#pragma unroll
            for (int mi = 0; mi < 2; mi++) {
                uint32_t off = SW128((uint32_t)((a_row + mi * 16) * 128 + ks * 32 + a_chb));
                LDSM_X4(a_lo8[mi][0], a_lo8[mi][1], a_lo8[mi][2], a_lo8[mi][3], s_a8 + off);
                uint32_t off2 = SW128((uint32_t)((a_row + mi * 16) * 128 + 64 + ks * 32 + a_chb));
                LDSM_X4(a_q8[mi][0], a_q8[mi][1], a_q8[mi][2], a_q8[mi][3], s_a8 + off2);
            }
#pragma unroll
            for (int p = 0; p < 4; p++) {
                uint32_t off = SW128((uint32_t)((b_row + p * 16) * 128 + ks * 32 + b_chb));
                uint32_t t0, t1, t2, t3;
                LDSM_X4(t0, t1, t2, t3, s_b8 + off);
                b_h8[2 * p][0] = t0; b_h8[2 * p][1] = t1;
                b_h8[2 * p + 1][0] = t2; b_h8[2 * p + 1][1] = t3;
                uint32_t off2 = SW128((uint32_t)((b_row + p * 16) * 128 + 64 + ks * 32 + b_chb));
                LDSM_X4(t0, t1, t2, t3, s_b8 + off2);
                b_l8[2 * p][0] = t0; b_l8[2 * p][1] = t1;
                b_l8[2 * p + 1][0] = t2; b_l8[2 * p + 1][1] = t3;
            }
            // pass2: H_lo8 x C_hi8
#pragma unroll
            for (int mi = 0; mi < 2; mi++)
#pragma unroll
                for (int ni = 0; ni < 8; ni++)
                    MMA_FP8(acc[mi][ni], a_lo8[mi], b_h8[ni]);
            // pass3: (H/32)_8 x (32*C_lo)_8
#pragma unroll
            for (int mi = 0; mi < 2; mi++)
#pragma unroll
                for (int ni = 0; ni < 8; ni++)
                    MMA_FP8(acc[mi][ni], a_q8[mi], b_l8[ni]);
        }
    }

    // epilogue: scale and store
#pragma unroll
    for (int mi = 0; mi < 2; mi++) {
#pragma unroll
        for (int ni = 0; ni < 8; ni++) {
            int row = m0 + wm * 32 + mi * 16 + (lane >> 2);
            int col = n0 + wn * 64 + ni * 8 + 2 * (lane & 3);
            float2 v0 = make_float2(acc[mi][ni][0] * OUT_SCALE,
                                    acc[mi][ni][1] * OUT_SCALE);
            float2 v1 = make_float2(acc[mi][ni][2] * OUT_SCALE,
                                    acc[mi][ni][3] * OUT_SCALE);
            *(float2*)(out + (size_t)row * OO + col) = v0;
            *(float2*)(out + (size_t)(row + 8) * OO + col) = v1;
        }
    }
}

// ---------------- launch --------------------------------------------------
extern "C" void kernel_launch(void* const* d_in, const int* in_sizes, int n_in,
                              void* d_out, int out_size) {
    const float* x  = (const float*)d_in[0];   // [B, S, D]
    const float* A  = (const float*)d_in[1];   // [D]
    const float* BC = (const float*)d_in[2];   // [D, O]
    float* out = (float*)d_out;                // [B, S, O]
    (void)in_sizes; (void)n_in; (void)out_size;

    int scan_threads = BB * NCH * DD / 2;      // 32768
    scan_carry_kernel<<<scan_threads / 128, 128>>>(x, A);
    scan_emit_kernel<<<scan_threads / 128, 128>>>(x, A);
    bc_transpose_split_kernel<<<dim3(OO / 32, DD / 32), dim3(32, 8)>>>(BC);

    cudaFuncSetAttribute(gemm_bf16_fp8_kernel,
                         cudaFuncAttributeMaxDynamicSharedMemorySize, SM_GEMM);
    dim3 grid((BB * SS) / TM, OO / TN);        // 128 x 8
    gemm_bf16_fp8_kernel<<<grid, 256, SM_GEMM>>>(out);
}